// round 6
// baseline (speedup 1.0000x reference)
#include <cuda_runtime.h>
#include <cuda_fp16.h>
#include <math.h>
#include <stdint.h>

#define L_SEQ 2048
#define DM    1024
#define DI    2048
#define DS    16
#define DTR   64
#define NX    96      // DTR + 2*DS

// ------------------------- scratch (device globals; no allocs) --------------
__device__ __align__(16) float g_x   [L_SEQ * DM];
__device__ __align__(16) float g_h   [L_SEQ * DM];
__device__ __align__(16) float g_xz  [L_SEQ * 2 * DI];
__device__ __align__(16) float g_xc  [L_SEQ * DI];
__device__ __align__(16) float g_xdbl[L_SEQ * NX];
__device__ __align__(16) float g_dt  [L_SEQ * DI];
__device__ __align__(16) float g_y   [L_SEQ * DI];

// fp16 double-K operand buffers
__device__ __align__(16) __half g_a2   [L_SEQ * 2 * DI];
__device__ __align__(16) __half g_w2   [2 * DI * 2 * DM];
__device__ __align__(16) __half g_head2[32000 * 2 * DM];

// split-K partials for x_proj
#define XP_PART (L_SEQ * NX)
__device__ __align__(16) float g_part[8 * XP_PART];

// ------------------------------ embedding -----------------------------------
__global__ void embed_kernel(const int* __restrict__ ids, const float* __restrict__ emb) {
    int row = blockIdx.x;
    int id  = ids[row];
    const float4* src = (const float4*)(emb + (size_t)id * DM);
    float4* dst = (float4*)(g_x + (size_t)row * DM);
    dst[threadIdx.x] = src[threadIdx.x];
}

// ------------------------------ layernorm -----------------------------------
__global__ __launch_bounds__(256)
void ln_kernel(const float* __restrict__ x, const float* __restrict__ g,
               const float* __restrict__ b, float* __restrict__ out) {
    int row = blockIdx.x;
    const float* xr = x + (size_t)row * DM;
    float v[4];
    float s = 0.f, s2 = 0.f;
#pragma unroll
    for (int j = 0; j < 4; j++) {
        v[j] = xr[j * 256 + threadIdx.x];
        s += v[j]; s2 += v[j] * v[j];
    }
#pragma unroll
    for (int o = 16; o > 0; o >>= 1) {
        s  += __shfl_xor_sync(0xffffffffu, s,  o);
        s2 += __shfl_xor_sync(0xffffffffu, s2, o);
    }
    __shared__ float rs[8], rs2[8];
    int w = threadIdx.x >> 5;
    if ((threadIdx.x & 31) == 0) { rs[w] = s; rs2[w] = s2; }
    __syncthreads();
    if (threadIdx.x < 32) {
        s  = (threadIdx.x < 8) ? rs[threadIdx.x]  : 0.f;
        s2 = (threadIdx.x < 8) ? rs2[threadIdx.x] : 0.f;
#pragma unroll
        for (int o = 4; o > 0; o >>= 1) {
            s  += __shfl_xor_sync(0xffffffffu, s,  o);
            s2 += __shfl_xor_sync(0xffffffffu, s2, o);
        }
        if (threadIdx.x == 0) { rs[0] = s; rs2[0] = s2; }
    }
    __syncthreads();
    float mean = rs[0] * (1.f / DM);
    float var  = rs2[0] * (1.f / DM) - mean * mean;
    float inv  = rsqrtf(var + 1e-5f);
#pragma unroll
    for (int j = 0; j < 4; j++) {
        int idx = j * 256 + threadIdx.x;
        out[(size_t)row * DM + idx] = (v[j] - mean) * inv * g[idx] + b[idx];
    }
}

// --------------------- fp32 -> fp16 double-K conversion ----------------------
__global__ __launch_bounds__(256)
void cvt2_kernel(const float* __restrict__ in, __half* __restrict__ out,
                 int kdiv8, int ld, int K2, int aside, int total) {
    int idx = blockIdx.x * 256 + threadIdx.x;
    if (idx >= total) return;
    int r = idx / kdiv8;
    int t = idx - r * kdiv8;
    const float4* p = (const float4*)(in + (size_t)r * ld + t * 8);
    float4 v0 = p[0], v1 = p[1];
    float a[8] = {v0.x, v0.y, v0.z, v0.w, v1.x, v1.y, v1.z, v1.w};
    __align__(16) __half o[16];
#pragma unroll
    for (int j = 0; j < 8; j++) {
        __half hi = __float2half(a[j]);
        __half lo = __float2half(a[j] - __half2float(hi));
        o[2 * j + 0] = hi;
        o[2 * j + 1] = aside ? lo : hi;
    }
    float4* q = (float4*)(out + (size_t)r * K2 + t * 16);
    q[0] = *(const float4*)&o[0];
    q[1] = *(const float4*)&o[8];
}

// ------------------------- mma.sync helpers ----------------------------------
__device__ __forceinline__ uint32_t smem_u32(const void* p) {
    uint32_t a;
    asm("{ .reg .u64 t; cvta.to.shared.u64 t, %1; cvt.u32.u64 %0, t; }" : "=r"(a) : "l"(p));
    return a;
}
__device__ __forceinline__ void cp16(uint32_t dst, const void* src, int nbytes) {
    asm volatile("cp.async.cg.shared.global [%0], [%1], 16, %2;"
                 :: "r"(dst), "l"(src), "r"(nbytes));
}
__device__ __forceinline__ void cp_commit() {
    asm volatile("cp.async.commit_group;" ::: "memory");
}
__device__ __forceinline__ void ldsm_x4(uint32_t* r, uint32_t addr) {
    asm volatile("ldmatrix.sync.aligned.m8n8.x4.shared.b16 {%0,%1,%2,%3}, [%4];"
                 : "=r"(r[0]), "=r"(r[1]), "=r"(r[2]), "=r"(r[3]) : "r"(addr));
}
__device__ __forceinline__ void mma16816(float* c, const uint32_t* a, const uint32_t* b) {
    asm volatile("mma.sync.aligned.m16n8k16.row.col.f32.f16.f16.f32 "
                 "{%0,%1,%2,%3}, {%4,%5,%6,%7}, {%8,%9}, {%0,%1,%2,%3};"
                 : "+f"(c[0]), "+f"(c[1]), "+f"(c[2]), "+f"(c[3])
                 : "r"(a[0]), "r"(a[1]), "r"(a[2]), "r"(a[3]), "r"(b[0]), "r"(b[1]));
}

// --------------------- HMMA GEMM:  C = A2 * B2^T -----------------------------
// Template BN: 128 (warp 64x32, occ2) or 256 (warp 64x64, occ1).
// Block 128xBN, 8 warps (2 x 4), BK=64, 3-stage cp.async pipeline.
#define BK     64
#define ROWB   144
#define ATILE  (128 * ROWB)
#define NSTAGE 3

template <int BN, int MINCTA>
__global__ __launch_bounds__(256, MINCTA)
void gemm_tc(const __half* __restrict__ A2, const __half* __restrict__ B2,
             float* __restrict__ C, int N, int K2, int ldc, int addC,
             int split, size_t partStride) {
    constexpr int NT    = BN / 32;                 // n8-tiles per warp: 4 or 8
    constexpr int BTILE = BN * ROWB;
    constexpr int BUFB  = ATILE + BTILE;
    constexpr int BU    = BN / 32;                 // B load units per thread (x256)

    extern __shared__ char sm[];
    uint32_t sbase = smem_u32(sm);

    int tid  = threadIdx.x;
    int lane = tid & 31;
    int wid  = tid >> 5;
    int wm   = wid & 1;
    int wn   = wid >> 1;                           // 0..3
    int m0   = blockIdx.x * 128;
    int n0   = blockIdx.y * BN;

    int NCtot = K2 / BK;
    int NC    = NCtot / split;
    int c0    = blockIdx.z * NC;
    C += (size_t)blockIdx.z * partStride;

    float acc[4][NT][4];
#pragma unroll
    for (int i = 0; i < 4; i++)
#pragma unroll
        for (int j = 0; j < NT; j++)
#pragma unroll
            for (int k = 0; k < 4; k++) acc[i][j][k] = 0.f;

    uint32_t a_ld = sbase + (uint32_t)((wm * 64 + (lane & 15)) * ROWB + (lane >> 4) * 16);
    uint32_t b_ld = sbase + (uint32_t)ATILE +
                    (uint32_t)((wn * (NT * 8) + ((lane >> 4) & 1) * 8 + (lane & 7)) * ROWB +
                               ((lane >> 3) & 1) * 16);

#define LOAD_CHUNK(c)                                                              \
    {                                                                              \
        int _c = (c);                                                              \
        uint32_t st = sbase + (uint32_t)((_c % NSTAGE) * BUFB);                    \
        const __half* Ag = A2 + (size_t)m0 * K2 + (size_t)(c0 + _c) * BK;          \
        const __half* Bg = B2 + (size_t)(c0 + _c) * BK;                            \
        _Pragma("unroll")                                                          \
        for (int u = 0; u < 4; u++) {                                              \
            int unit = u * 256 + tid;                                              \
            int row = unit >> 3, q = unit & 7;                                     \
            cp16(st + row * ROWB + q * 16, Ag + (size_t)row * K2 + q * 8, 16);     \
        }                                                                          \
        _Pragma("unroll")                                                          \
        for (int u = 0; u < BU; u++) {                                             \
            int unit = u * 256 + tid;                                              \
            int row = unit >> 3, q = unit & 7;                                     \
            int rb = n0 + row;                                                     \
            int v = (rb < N) ? 16 : 0;                                             \
            int rc = (rb < N) ? rb : 0;                                            \
            cp16(st + ATILE + row * ROWB + q * 16,                                 \
                 Bg + (size_t)rc * K2 + q * 8, v);                                 \
        }                                                                          \
        cp_commit();                                                               \
    }

    LOAD_CHUNK(0);
    if (NC > 1) LOAD_CHUNK(1);

    for (int c = 0; c < NC; c++) {
        if (c + 1 < NC) asm volatile("cp.async.wait_group 1;" ::: "memory");
        else            asm volatile("cp.async.wait_group 0;" ::: "memory");
        __syncthreads();
        if (c + 2 < NC) LOAD_CHUNK(c + 2);

        uint32_t boff = (uint32_t)((c % NSTAGE) * BUFB);
#pragma unroll
        for (int ks = 0; ks < 4; ks++) {
            uint32_t ka = a_ld + boff + ks * 32;
            uint32_t kb = b_ld + boff + ks * 32;
            uint32_t af[4][4];
#pragma unroll
            for (int mt = 0; mt < 4; mt++) ldsm_x4(af[mt], ka + mt * 16 * ROWB);
            uint32_t bf[NT / 2][4];
#pragma unroll
            for (int p = 0; p < NT / 2; p++) ldsm_x4(bf[p], kb + p * 16 * ROWB);
#pragma unroll
            for (int mt = 0; mt < 4; mt++)
#pragma unroll
                for (int nt = 0; nt < NT; nt++)
                    mma16816(acc[mt][nt], af[mt], &bf[nt >> 1][(nt & 1) * 2]);
        }
    }
#undef LOAD_CHUNK

    int g  = lane >> 2;
    int tg = (lane & 3) * 2;
#pragma unroll
    for (int mt = 0; mt < 4; mt++) {
        int r0 = m0 + wm * 64 + mt * 16 + g;
#pragma unroll
        for (int nt = 0; nt < NT; nt++) {
            int col = n0 + wn * (NT * 8) + nt * 8 + tg;
            if (col < N) {
                float* p0 = C + (size_t)r0 * ldc + col;
                float* p1 = p0 + 8 * (size_t)ldc;
                float2 v0 = make_float2(acc[mt][nt][0], acc[mt][nt][1]);
                float2 v1 = make_float2(acc[mt][nt][2], acc[mt][nt][3]);
                if (addC) {
                    float2 o0 = *(float2*)p0, o1 = *(float2*)p1;
                    v0.x += o0.x; v0.y += o0.y; v1.x += o1.x; v1.y += o1.y;
                }
                *(float2*)p0 = v0;
                *(float2*)p1 = v1;
            }
        }
    }
}

#define GEMM_SMEM_128 (NSTAGE * (ATILE + 128 * ROWB))   // 110592
#define GEMM_SMEM_256 (NSTAGE * (ATILE + 256 * ROWB))   // 165888

// --------------------- split-K partial reduction (x_proj) --------------------
__global__ void reduce_part_kernel() {
    int i = blockIdx.x * 256 + threadIdx.x;
    float s = 0.f;
#pragma unroll
    for (int z = 0; z < 8; z++) s += g_part[z * XP_PART + i];
    g_xdbl[i] = s;
}

// ------------------------------ conv1d(4) + silu -----------------------------
__global__ void conv_kernel(const float* __restrict__ cw, const float* __restrict__ cb) {
    int i = blockIdx.x * 256 + threadIdx.x;
    int l = i / DI, d = i % DI;
    float acc = cb[d];
#pragma unroll
    for (int k = 0; k < 4; k++) {
        int li = l + k - 3;
        if (li >= 0) acc += g_xz[(size_t)li * (2 * DI) + d] * cw[d * 4 + k];
    }
    g_xc[i] = acc / (1.f + expf(-acc));
}

// ------------------------------ dt bias + softplus ---------------------------
__global__ void softplus_kernel(const float* __restrict__ dtb) {
    int i = blockIdx.x * 256 + threadIdx.x;
    int d = i % DI;
    float v = g_dt[i] + dtb[d];
    g_dt[i] = (v > 20.f) ? v : log1pf(expf(v));
}

// ------------------------------ selective scan -------------------------------
__global__ __launch_bounds__(256)
void scan_kernel(const float* __restrict__ A_log, float* __restrict__ y) {
    int dloc = threadIdx.x >> 4;
    int n    = threadIdx.x & 15;
    int dbase = blockIdx.x * 16;
    int d = dbase + dloc;
    float a = -__expf(A_log[d * DS + n]);
    float h = 0.f;

    __shared__ float sB[64][16], sC[64][16], sdt[64][16], sxc[64][16];

    for (int l0 = 0; l0 < L_SEQ; l0 += 64) {
        __syncthreads();
        for (int i = threadIdx.x; i < 64 * 16; i += 256) {
            int t = i >> 4, j = i & 15;
            int l = l0 + t;
            sB [t][j] = g_xdbl[(size_t)l * NX + DTR + j];
            sC [t][j] = g_xdbl[(size_t)l * NX + DTR + DS + j];
            sdt[t][j] = g_dt[(size_t)l * DI + dbase + j];
            sxc[t][j] = g_xc[(size_t)l * DI + dbase + j];
        }
        __syncthreads();
#pragma unroll 4
        for (int t = 0; t < 64; t++) {
            float dtv = sdt[t][dloc];
            float xv  = sxc[t][dloc];
            float b   = sB[t][n];
            float c   = sC[t][n];
            h = __expf(dtv * a) * h + dtv * b * xv;
            float p = h * c;
            p += __shfl_xor_sync(0xffffffffu, p, 8, 16);
            p += __shfl_xor_sync(0xffffffffu, p, 4, 16);
            p += __shfl_xor_sync(0xffffffffu, p, 2, 16);
            p += __shfl_xor_sync(0xffffffffu, p, 1, 16);
            if (n == 0) y[(size_t)(l0 + t) * DI + d] = p;
        }
    }
}

// ------------------------------ D-skip + z-gate ------------------------------
__global__ void gate_kernel(const float* __restrict__ dsk) {
    int i = blockIdx.x * 256 + threadIdx.x;
    int l = i / DI, d = i % DI;
    float z  = g_xz[(size_t)l * (2 * DI) + DI + d];
    float sz = z / (1.f + expf(-z));
    g_y[i] = (g_y[i] + dsk[d] * g_xc[i]) * sz;
}

// ============================================================================
static void launch_cvt2(const float* in, __half* out, int R, int K, int ld, int aside) {
    int total = R * (K / 8);
    cvt2_kernel<<<(total + 255) / 256, 256>>>(in, out, K / 8, ld, 2 * K, aside, total);
}

extern "C" void kernel_launch(void* const* d_in, const int* in_sizes, int n_in,
                              void* d_out, int out_size) {
    const int*   ids  = (const int*)  d_in[0];
    const float* emb  = (const float*)d_in[1];
    const float* ln_g = (const float*)d_in[2];
    const float* ln_b = (const float*)d_in[3];
    const float* inw  = (const float*)d_in[4];
    const float* cw   = (const float*)d_in[5];
    const float* cb   = (const float*)d_in[6];
    const float* xpw  = (const float*)d_in[7];
    const float* dtw  = (const float*)d_in[8];
    const float* dtb  = (const float*)d_in[9];
    const float* alog = (const float*)d_in[10];
    const float* dsk  = (const float*)d_in[11];
    const float* outw = (const float*)d_in[12];
    const float* lnfg = (const float*)d_in[13];
    const float* lnfb = (const float*)d_in[14];
    const float* hw   = (const float*)d_in[15];
    float* out = (float*)d_out;

    cudaFuncSetAttribute(gemm_tc<128, 2>, cudaFuncAttributeMaxDynamicSharedMemorySize, GEMM_SMEM_128);
    cudaFuncSetAttribute(gemm_tc<256, 1>, cudaFuncAttributeMaxDynamicSharedMemorySize, GEMM_SMEM_256);

    float *px, *ph, *pxz, *pxc, *pxdbl, *pdt, *py, *ppart;
    __half *pa2, *pw2, *phead2;
    cudaGetSymbolAddress((void**)&px,    g_x);
    cudaGetSymbolAddress((void**)&ph,    g_h);
    cudaGetSymbolAddress((void**)&pxz,   g_xz);
    cudaGetSymbolAddress((void**)&pxc,   g_xc);
    cudaGetSymbolAddress((void**)&pxdbl, g_xdbl);
    cudaGetSymbolAddress((void**)&pdt,   g_dt);
    cudaGetSymbolAddress((void**)&py,    g_y);
    cudaGetSymbolAddress((void**)&pa2,   g_a2);
    cudaGetSymbolAddress((void**)&pw2,   g_w2);
    cudaGetSymbolAddress((void**)&phead2, g_head2);
    cudaGetSymbolAddress((void**)&ppart, g_part);

    const int EW_BLOCKS = (L_SEQ * DI) / 256;

    embed_kernel<<<L_SEQ, 256>>>(ids, emb);

    for (int l = 0; l < 2; l++) {
        ln_kernel<<<L_SEQ, 256>>>(px, ln_g + l * DM, ln_b + l * DM, ph);

        // in_proj: [2048,1024] x [4096,1024]^T  — big tile
        launch_cvt2(ph, pa2, L_SEQ, DM, DM, 1);
        launch_cvt2(inw + (size_t)l * 2 * DI * DM, pw2, 2 * DI, DM, DM, 0);
        gemm_tc<256, 1><<<dim3(16, 16), 256, GEMM_SMEM_256>>>(pa2, pw2, pxz, 2 * DI, 2 * DM, 2 * DI, 0, 1, 0);

        conv_kernel<<<EW_BLOCKS, 256>>>(cw + (size_t)l * DI * 4, cb + (size_t)l * DI);

        // x_proj: split-K=8
        launch_cvt2(pxc, pa2, L_SEQ, DI, DI, 1);
        launch_cvt2(xpw + (size_t)l * NX * DI, pw2, NX, DI, DI, 0);
        gemm_tc<128, 2><<<dim3(16, 1, 8), 256, GEMM_SMEM_128>>>(pa2, pw2, ppart, NX, 2 * DI, NX, 0, 8, XP_PART);
        reduce_part_kernel<<<(L_SEQ * NX) / 256, 256>>>();

        // dt_proj: [2048,64] x [2048,64]^T
        launch_cvt2(pxdbl, pa2, L_SEQ, DTR, NX, 1);
        launch_cvt2(dtw + (size_t)l * DI * DTR, pw2, DI, DTR, DTR, 0);
        gemm_tc<128, 2><<<dim3(16, 16), 256, GEMM_SMEM_128>>>(pa2, pw2, pdt, DI, 2 * DTR, DI, 0, 1, 0);

        softplus_kernel<<<EW_BLOCKS, 256>>>(dtb + (size_t)l * DI);
        scan_kernel<<<DI / 16, 256>>>(alog + (size_t)l * DI * DS, py);
        gate_kernel<<<EW_BLOCKS, 256>>>(dsk + (size_t)l * DI);

        // out_proj with residual
        launch_cvt2(py, pa2, L_SEQ, DI, DI, 1);
        launch_cvt2(outw + (size_t)l * DM * DI, pw2, DM, DI, DI, 0);
        gemm_tc<128, 2><<<dim3(16, 8), 256, GEMM_SMEM_128>>>(pa2, pw2, px, DM, 2 * DI, DM, 1, 1, 0);
    }

    // final layernorm + head (big tile)
    ln_kernel<<<L_SEQ, 256>>>(px, lnfg, lnfb, ph);
    launch_cvt2(ph, pa2, L_SEQ, DM, DM, 1);
    launch_cvt2(hw, phead2, 32000, DM, DM, 0);
    gemm_tc<256, 1><<<dim3(16, 125), 256, GEMM_SMEM_256>>>(pa2, phead2, out, 32000, 2 * DM, 32000, 0, 1, 0);
}

// round 7
// speedup vs baseline: 1.0174x; 1.0174x over previous
#include <cuda_runtime.h>
#include <cuda_fp16.h>
#include <math.h>
#include <stdint.h>

#define L_SEQ 2048
#define DM    1024
#define DI    2048
#define DS    16
#define DTR   64
#define NX    96      // DTR + 2*DS

// ------------------------- scratch (device globals; no allocs) --------------
__device__ __align__(16) float g_x   [L_SEQ * DM];
__device__ __align__(16) float g_h   [L_SEQ * DM];
__device__ __align__(16) float g_xz  [L_SEQ * 2 * DI];
__device__ __align__(16) float g_xc  [L_SEQ * DI];
__device__ __align__(16) float g_xdbl[L_SEQ * NX];
__device__ __align__(16) float g_dt  [L_SEQ * DI];
__device__ __align__(16) float g_y   [L_SEQ * DI];

// split-K partials for x_proj
#define XP_PART (L_SEQ * NX)
__device__ __align__(16) float g_part[8 * XP_PART];

// ------------------------------ embedding -----------------------------------
__global__ void embed_kernel(const int* __restrict__ ids, const float* __restrict__ emb) {
    int row = blockIdx.x;
    int id  = ids[row];
    const float4* src = (const float4*)(emb + (size_t)id * DM);
    float4* dst = (float4*)(g_x + (size_t)row * DM);
    dst[threadIdx.x] = src[threadIdx.x];
}

// ------------------------------ layernorm -----------------------------------
__global__ __launch_bounds__(256)
void ln_kernel(const float* __restrict__ x, const float* __restrict__ g,
               const float* __restrict__ b, float* __restrict__ out) {
    int row = blockIdx.x;
    const float* xr = x + (size_t)row * DM;
    float v[4];
    float s = 0.f, s2 = 0.f;
#pragma unroll
    for (int j = 0; j < 4; j++) {
        v[j] = xr[j * 256 + threadIdx.x];
        s += v[j]; s2 += v[j] * v[j];
    }
#pragma unroll
    for (int o = 16; o > 0; o >>= 1) {
        s  += __shfl_xor_sync(0xffffffffu, s,  o);
        s2 += __shfl_xor_sync(0xffffffffu, s2, o);
    }
    __shared__ float rs[8], rs2[8];
    int w = threadIdx.x >> 5;
    if ((threadIdx.x & 31) == 0) { rs[w] = s; rs2[w] = s2; }
    __syncthreads();
    if (threadIdx.x < 32) {
        s  = (threadIdx.x < 8) ? rs[threadIdx.x]  : 0.f;
        s2 = (threadIdx.x < 8) ? rs2[threadIdx.x] : 0.f;
#pragma unroll
        for (int o = 4; o > 0; o >>= 1) {
            s  += __shfl_xor_sync(0xffffffffu, s,  o);
            s2 += __shfl_xor_sync(0xffffffffu, s2, o);
        }
        if (threadIdx.x == 0) { rs[0] = s; rs2[0] = s2; }
    }
    __syncthreads();
    float mean = rs[0] * (1.f / DM);
    float var  = rs2[0] * (1.f / DM) - mean * mean;
    float inv  = rsqrtf(var + 1e-5f);
#pragma unroll
    for (int j = 0; j < 4; j++) {
        int idx = j * 256 + threadIdx.x;
        out[(size_t)row * DM + idx] = (v[j] - mean) * inv * g[idx] + b[idx];
    }
}

// ------------------------- mma.sync helpers ----------------------------------
__device__ __forceinline__ uint32_t smem_u32(const void* p) {
    uint32_t a;
    asm("{ .reg .u64 t; cvta.to.shared.u64 t, %1; cvt.u32.u64 %0, t; }" : "=r"(a) : "l"(p));
    return a;
}
__device__ __forceinline__ void ldsm_x4(uint32_t* r, uint32_t addr) {
    asm volatile("ldmatrix.sync.aligned.m8n8.x4.shared.b16 {%0,%1,%2,%3}, [%4];"
                 : "=r"(r[0]), "=r"(r[1]), "=r"(r[2]), "=r"(r[3]) : "r"(addr));
}
__device__ __forceinline__ void mma16816(float* c, const uint32_t* a, const uint32_t* b) {
    asm volatile("mma.sync.aligned.m16n8k16.row.col.f32.f16.f16.f32 "
                 "{%0,%1,%2,%3}, {%4,%5,%6,%7}, {%8,%9}, {%0,%1,%2,%3};"
                 : "+f"(c[0]), "+f"(c[1]), "+f"(c[2]), "+f"(c[3])
                 : "r"(a[0]), "r"(a[1]), "r"(a[2]), "r"(a[3]), "r"(b[0]), "r"(b[1]));
}
// pack fp32 -> two fp16: {hi, lo} (A side)
__device__ __forceinline__ uint32_t pack_hl(float x) {
    __half h = __float2half(x);
    __half l = __float2half(x - __half2float(h));
    return (uint32_t)__half_as_ushort(h) | ((uint32_t)__half_as_ushort(l) << 16);
}
// pack fp32 -> two fp16: {hi, hi} (B side)
__device__ __forceinline__ uint32_t pack_hh(float x) {
    uint32_t u = (uint32_t)__half_as_ushort(__float2half(x));
    return u | (u << 16);
}

// --------------- HMMA GEMM with fused fp32->split-fp16:  C = A * B^T ---------
// A [M,K] fp32 (lda), B [N,K] fp32 (ldb), C [M,N] fp32 (ldc).
// Internally: A2 = {hi,lo} interleave, B2 = {hi,hi} -> K2 = 2K fp16 HMMA.
// Block 128x128, 8 warps (warp 64x32), chunk = 32 fp32 cols = 64 fp16 cols,
// double-buffered smem, register-staged LDG prefetch.
// mode: 0 = store, 1 = add (residual), 2 = softplus(acc + bias[col]).
// K % 32 == 0, M % 128 == 0; N arbitrary (guards).
#define BKF   32                    // fp32 cols per chunk
#define ROWB  144                   // smem row bytes (64 fp16 = 128B + 16 pad)
#define ATILE (128 * ROWB)
#define BUFB  (2 * ATILE)           // A + B per stage
#define GEMM_SMEM (2 * BUFB)        // 73728

__global__ __launch_bounds__(256, 2)
void gemm_tc(const float* __restrict__ A, const float* __restrict__ B,
             float* __restrict__ C, int N, int K,
             int lda, int ldb, int ldc,
             int mode, const float* __restrict__ bias,
             int split, size_t partStride) {
    extern __shared__ char sm[];
    uint32_t sbase = smem_u32(sm);

    int tid  = threadIdx.x;
    int lane = tid & 31;
    int wid  = tid >> 5;
    int wm   = wid & 1;
    int wn   = wid >> 1;
    int m0   = blockIdx.x * 128;
    int n0   = blockIdx.y * 128;

    int NCtot = K / BKF;
    int NC    = NCtot / split;
    int c0    = blockIdx.z * NC;
    C += (size_t)blockIdx.z * partStride;

    int lrow = tid >> 3;            // 0..31 base row (row = lrow + 32*u)
    int q    = tid & 7;             // 0..7  float4 index within 32 fp32 cols? no:
    // mapping: unit = u*256 + tid; row = unit>>3 = (u*32 + (tid>>3)); q = tid&7.
    int rbB  = n0 + lrow;           // recomputed per u below

    float acc[4][4][4];
#pragma unroll
    for (int i = 0; i < 4; i++)
#pragma unroll
        for (int j = 0; j < 4; j++)
#pragma unroll
            for (int k = 0; k < 4; k++) acc[i][j][k] = 0.f;

    uint32_t a_ld = sbase + (uint32_t)((wm * 64 + (lane & 15)) * ROWB + (lane >> 4) * 16);
    uint32_t b_ld = sbase + (uint32_t)ATILE +
                    (uint32_t)((wn * 32 + ((lane >> 4) & 1) * 8 + (lane & 7)) * ROWB +
                               ((lane >> 3) & 1) * 16);

    float4 sa[4], sb[4];

#define LDG_CHUNK(c)                                                               \
    {                                                                              \
        int _cc = c0 + (c);                                                        \
        const float* Ag = A + (size_t)m0 * lda + (size_t)_cc * BKF;                \
        const float* Bg = B + (size_t)_cc * BKF;                                   \
        _Pragma("unroll")                                                          \
        for (int u = 0; u < 4; u++) {                                              \
            int row = u * 32 + lrow;                                               \
            sa[u] = *(const float4*)(Ag + (size_t)row * lda + q * 4);              \
        }                                                                          \
        _Pragma("unroll")                                                          \
        for (int u = 0; u < 4; u++) {                                              \
            int row = u * 32 + lrow;                                               \
            int rb = n0 + row;                                                     \
            int rc = (rb < N) ? rb : 0;                                            \
            sb[u] = *(const float4*)(Bg + (size_t)rc * ldb + q * 4);               \
        }                                                                          \
    }

#define STS_CHUNK(c)                                                               \
    {                                                                              \
        char* st = sm + (size_t)(((c) & 1) * BUFB);                                \
        _Pragma("unroll")                                                          \
        for (int u = 0; u < 4; u++) {                                              \
            int row = u * 32 + lrow;                                               \
            uint4 w;                                                               \
            w.x = pack_hl(sa[u].x); w.y = pack_hl(sa[u].y);                        \
            w.z = pack_hl(sa[u].z); w.w = pack_hl(sa[u].w);                        \
            *(uint4*)(st + row * ROWB + q * 16) = w;                               \
        }                                                                          \
        _Pragma("unroll")                                                          \
        for (int u = 0; u < 4; u++) {                                              \
            int row = u * 32 + lrow;                                               \
            uint4 w;                                                               \
            w.x = pack_hh(sb[u].x); w.y = pack_hh(sb[u].y);                        \
            w.z = pack_hh(sb[u].z); w.w = pack_hh(sb[u].w);                        \
            *(uint4*)(st + ATILE + row * ROWB + q * 16) = w;                       \
        }                                                                          \
    }

    LDG_CHUNK(0);

    for (int c = 0; c < NC; c++) {
        STS_CHUNK(c);
        __syncthreads();
        if (c + 1 < NC) LDG_CHUNK(c + 1);

        uint32_t boff = (uint32_t)((c & 1) * BUFB);
#pragma unroll
        for (int ks = 0; ks < 4; ks++) {
            uint32_t ka = a_ld + boff + ks * 32;
            uint32_t kb = b_ld + boff + ks * 32;
            uint32_t af[4][4];
#pragma unroll
            for (int mt = 0; mt < 4; mt++) ldsm_x4(af[mt], ka + mt * 16 * ROWB);
            uint32_t bf[2][4];
#pragma unroll
            for (int p = 0; p < 2; p++) ldsm_x4(bf[p], kb + p * 16 * ROWB);
#pragma unroll
            for (int mt = 0; mt < 4; mt++)
#pragma unroll
                for (int nt = 0; nt < 4; nt++)
                    mma16816(acc[mt][nt], af[mt], &bf[nt >> 1][(nt & 1) * 2]);
        }
    }
#undef LDG_CHUNK
#undef STS_CHUNK

    int g  = lane >> 2;
    int tg = (lane & 3) * 2;
#pragma unroll
    for (int mt = 0; mt < 4; mt++) {
        int r0 = m0 + wm * 64 + mt * 16 + g;
#pragma unroll
        for (int nt = 0; nt < 4; nt++) {
            int col = n0 + wn * 32 + nt * 8 + tg;
            if (col < N) {
                float* p0 = C + (size_t)r0 * ldc + col;
                float* p1 = p0 + 8 * (size_t)ldc;
                float2 v0 = make_float2(acc[mt][nt][0], acc[mt][nt][1]);
                float2 v1 = make_float2(acc[mt][nt][2], acc[mt][nt][3]);
                if (mode == 1) {
                    float2 o0 = *(float2*)p0, o1 = *(float2*)p1;
                    v0.x += o0.x; v0.y += o0.y; v1.x += o1.x; v1.y += o1.y;
                } else if (mode == 2) {
                    float b0 = bias[col], b1 = bias[col + 1];
                    float t;
                    t = v0.x + b0; v0.x = (t > 20.f) ? t : log1pf(expf(t));
                    t = v0.y + b1; v0.y = (t > 20.f) ? t : log1pf(expf(t));
                    t = v1.x + b0; v1.x = (t > 20.f) ? t : log1pf(expf(t));
                    t = v1.y + b1; v1.y = (t > 20.f) ? t : log1pf(expf(t));
                }
                *(float2*)p0 = v0;
                *(float2*)p1 = v1;
            }
        }
    }
}

// --------------------- split-K partial reduction (x_proj) --------------------
__global__ void reduce_part_kernel() {
    int i = blockIdx.x * 256 + threadIdx.x;
    float s = 0.f;
#pragma unroll
    for (int z = 0; z < 8; z++) s += g_part[z * XP_PART + i];
    g_xdbl[i] = s;
}

// ------------------------------ conv1d(4) + silu -----------------------------
__global__ void conv_kernel(const float* __restrict__ cw, const float* __restrict__ cb) {
    int i = blockIdx.x * 256 + threadIdx.x;
    int l = i / DI, d = i % DI;
    float acc = cb[d];
#pragma unroll
    for (int k = 0; k < 4; k++) {
        int li = l + k - 3;
        if (li >= 0) acc += g_xz[(size_t)li * (2 * DI) + d] * cw[d * 4 + k];
    }
    g_xc[i] = acc / (1.f + expf(-acc));
}

// ------------------------------ selective scan -------------------------------
__global__ __launch_bounds__(256)
void scan_kernel(const float* __restrict__ A_log, float* __restrict__ y) {
    int dloc = threadIdx.x >> 4;
    int n    = threadIdx.x & 15;
    int dbase = blockIdx.x * 16;
    int d = dbase + dloc;
    float a = -__expf(A_log[d * DS + n]);
    float h = 0.f;

    __shared__ float sB[64][16], sC[64][16], sdt[64][16], sxc[64][16];

    for (int l0 = 0; l0 < L_SEQ; l0 += 64) {
        __syncthreads();
        for (int i = threadIdx.x; i < 64 * 16; i += 256) {
            int t = i >> 4, j = i & 15;
            int l = l0 + t;
            sB [t][j] = g_xdbl[(size_t)l * NX + DTR + j];
            sC [t][j] = g_xdbl[(size_t)l * NX + DTR + DS + j];
            sdt[t][j] = g_dt[(size_t)l * DI + dbase + j];
            sxc[t][j] = g_xc[(size_t)l * DI + dbase + j];
        }
        __syncthreads();
#pragma unroll 4
        for (int t = 0; t < 64; t++) {
            float dtv = sdt[t][dloc];
            float xv  = sxc[t][dloc];
            float b   = sB[t][n];
            float c   = sC[t][n];
            h = __expf(dtv * a) * h + dtv * b * xv;
            float p = h * c;
            p += __shfl_xor_sync(0xffffffffu, p, 8, 16);
            p += __shfl_xor_sync(0xffffffffu, p, 4, 16);
            p += __shfl_xor_sync(0xffffffffu, p, 2, 16);
            p += __shfl_xor_sync(0xffffffffu, p, 1, 16);
            if (n == 0) y[(size_t)(l0 + t) * DI + d] = p;
        }
    }
}

// ------------------------------ D-skip + z-gate ------------------------------
__global__ void gate_kernel(const float* __restrict__ dsk) {
    int i = blockIdx.x * 256 + threadIdx.x;
    int l = i / DI, d = i % DI;
    float z  = g_xz[(size_t)l * (2 * DI) + DI + d];
    float sz = z / (1.f + expf(-z));
    g_y[i] = (g_y[i] + dsk[d] * g_xc[i]) * sz;
}

// ============================================================================
extern "C" void kernel_launch(void* const* d_in, const int* in_sizes, int n_in,
                              void* d_out, int out_size) {
    const int*   ids  = (const int*)  d_in[0];
    const float* emb  = (const float*)d_in[1];
    const float* ln_g = (const float*)d_in[2];
    const float* ln_b = (const float*)d_in[3];
    const float* inw  = (const float*)d_in[4];
    const float* cw   = (const float*)d_in[5];
    const float* cb   = (const float*)d_in[6];
    const float* xpw  = (const float*)d_in[7];
    const float* dtw  = (const float*)d_in[8];
    const float* dtb  = (const float*)d_in[9];
    const float* alog = (const float*)d_in[10];
    const float* dsk  = (const float*)d_in[11];
    const float* outw = (const float*)d_in[12];
    const float* lnfg = (const float*)d_in[13];
    const float* lnfb = (const float*)d_in[14];
    const float* hw   = (const float*)d_in[15];
    float* out = (float*)d_out;

    cudaFuncSetAttribute(gemm_tc, cudaFuncAttributeMaxDynamicSharedMemorySize, GEMM_SMEM);

    float *px, *ph, *pxz, *pxc, *pxdbl, *pdt, *py, *ppart;
    cudaGetSymbolAddress((void**)&px,    g_x);
    cudaGetSymbolAddress((void**)&ph,    g_h);
    cudaGetSymbolAddress((void**)&pxz,   g_xz);
    cudaGetSymbolAddress((void**)&pxc,   g_xc);
    cudaGetSymbolAddress((void**)&pxdbl, g_xdbl);
    cudaGetSymbolAddress((void**)&pdt,   g_dt);
    cudaGetSymbolAddress((void**)&py,    g_y);
    cudaGetSymbolAddress((void**)&ppart, g_part);

    const int EW_BLOCKS = (L_SEQ * DI) / 256;

    embed_kernel<<<L_SEQ, 256>>>(ids, emb);

    for (int l = 0; l < 2; l++) {
        ln_kernel<<<L_SEQ, 256>>>(px, ln_g + l * DM, ln_b + l * DM, ph);

        // in_proj: [2048,1024] x [4096,1024]^T -> xz
        gemm_tc<<<dim3(16, 32), 256, GEMM_SMEM>>>(
            ph, inw + (size_t)l * 2 * DI * DM, pxz,
            2 * DI, DM, DM, DM, 2 * DI, 0, nullptr, 1, 0);

        conv_kernel<<<EW_BLOCKS, 256>>>(cw + (size_t)l * DI * 4, cb + (size_t)l * DI);

        // x_proj: [2048,2048] x [96,2048]^T  split-K=8 -> partials -> reduce
        gemm_tc<<<dim3(16, 1, 8), 256, GEMM_SMEM>>>(
            pxc, xpw + (size_t)l * NX * DI, ppart,
            NX, DI, DI, DI, NX, 0, nullptr, 8, XP_PART);
        reduce_part_kernel<<<(L_SEQ * NX) / 256, 256>>>();

        // dt_proj: [2048,64] x [2048,64]^T, fused softplus(acc + dtb)
        gemm_tc<<<dim3(16, 16), 256, GEMM_SMEM>>>(
            pxdbl, dtw + (size_t)l * DI * DTR, pdt,
            DI, DTR, NX, DTR, DI, 2, dtb + (size_t)l * DI, 1, 0);

        scan_kernel<<<DI / 16, 256>>>(alog + (size_t)l * DI * DS, py);
        gate_kernel<<<EW_BLOCKS, 256>>>(dsk + (size_t)l * DI);

        // out_proj with residual: x += [2048,2048] x [1024,2048]^T
        gemm_tc<<<dim3(16, 8), 256, GEMM_SMEM>>>(
            py, outw + (size_t)l * DM * DI, px,
            DM, DI, DI, DI, DM, 1, nullptr, 1, 0);
    }

    // final layernorm + head
    ln_kernel<<<L_SEQ, 256>>>(px, lnfg, lnfb, ph);
    gemm_tc<<<dim3(16, 250), 256, GEMM_SMEM>>>(
        ph, hw, out, 32000, DM, DM, DM, 32000, 0, nullptr, 1, 0);
}

// round 8
// speedup vs baseline: 1.2046x; 1.1840x over previous
#include <cuda_runtime.h>
#include <cuda_fp16.h>
#include <math.h>
#include <stdint.h>

#define L_SEQ 2048
#define DM    1024
#define DI    2048
#define DS    16
#define DTR   64
#define NX    96      // DTR + 2*DS

// ------------------------- scratch (device globals; no allocs) --------------
__device__ __align__(16) float g_x   [L_SEQ * DM];
__device__ __align__(16) float g_h   [L_SEQ * DM];
__device__ __align__(16) float g_xz  [L_SEQ * 2 * DI];
__device__ __align__(16) float g_xc  [L_SEQ * DI];
__device__ __align__(16) float g_xdbl[L_SEQ * NX];
__device__ __align__(16) float g_dt  [L_SEQ * DI];
__device__ __align__(16) float g_y   [L_SEQ * DI];

// fp16 double-K operand buffers
__device__ __align__(16) __half g_a2   [L_SEQ * 2 * DI];
__device__ __align__(16) __half g_w2   [2 * DI * 2 * DM];
__device__ __align__(16) __half g_head2[32000 * 2 * DM];

// split-K partials for x_proj
#define XP_PART (L_SEQ * NX)
__device__ __align__(16) float g_part[8 * XP_PART];

// ------------------------------ embedding -----------------------------------
__global__ void embed_kernel(const int* __restrict__ ids, const float* __restrict__ emb) {
    int row = blockIdx.x;
    int id  = ids[row];
    const float4* src = (const float4*)(emb + (size_t)id * DM);
    float4* dst = (float4*)(g_x + (size_t)row * DM);
    dst[threadIdx.x] = src[threadIdx.x];
}

// ------------------------------ layernorm -----------------------------------
__global__ __launch_bounds__(256)
void ln_kernel(const float* __restrict__ x, const float* __restrict__ g,
               const float* __restrict__ b, float* __restrict__ out) {
    int row = blockIdx.x;
    const float* xr = x + (size_t)row * DM;
    float v[4];
    float s = 0.f, s2 = 0.f;
#pragma unroll
    for (int j = 0; j < 4; j++) {
        v[j] = xr[j * 256 + threadIdx.x];
        s += v[j]; s2 += v[j] * v[j];
    }
#pragma unroll
    for (int o = 16; o > 0; o >>= 1) {
        s  += __shfl_xor_sync(0xffffffffu, s,  o);
        s2 += __shfl_xor_sync(0xffffffffu, s2, o);
    }
    __shared__ float rs[8], rs2[8];
    int w = threadIdx.x >> 5;
    if ((threadIdx.x & 31) == 0) { rs[w] = s; rs2[w] = s2; }
    __syncthreads();
    if (threadIdx.x < 32) {
        s  = (threadIdx.x < 8) ? rs[threadIdx.x]  : 0.f;
        s2 = (threadIdx.x < 8) ? rs2[threadIdx.x] : 0.f;
#pragma unroll
        for (int o = 4; o > 0; o >>= 1) {
            s  += __shfl_xor_sync(0xffffffffu, s,  o);
            s2 += __shfl_xor_sync(0xffffffffu, s2, o);
        }
        if (threadIdx.x == 0) { rs[0] = s; rs2[0] = s2; }
    }
    __syncthreads();
    float mean = rs[0] * (1.f / DM);
    float var  = rs2[0] * (1.f / DM) - mean * mean;
    float inv  = rsqrtf(var + 1e-5f);
#pragma unroll
    for (int j = 0; j < 4; j++) {
        int idx = j * 256 + threadIdx.x;
        out[(size_t)row * DM + idx] = (v[j] - mean) * inv * g[idx] + b[idx];
    }
}

// --------------------- fp32 -> fp16 double-K conversion ----------------------
// in [R,K] (row stride ld) -> out [R,2K]:
//   aside=1 (A operand): {hi, lo},  aside=0 (B operand): {hi, hi}
__global__ __launch_bounds__(256)
void cvt2_kernel(const float* __restrict__ in, __half* __restrict__ out,
                 int kdiv8, int ld, int K2, int aside, int total) {
    int idx = blockIdx.x * 256 + threadIdx.x;
    if (idx >= total) return;
    int r = idx / kdiv8;
    int t = idx - r * kdiv8;
    const float4* p = (const float4*)(in + (size_t)r * ld + t * 8);
    float4 v0 = p[0], v1 = p[1];
    float a[8] = {v0.x, v0.y, v0.z, v0.w, v1.x, v1.y, v1.z, v1.w};
    __align__(16) __half o[16];
#pragma unroll
    for (int j = 0; j < 8; j++) {
        __half hi = __float2half(a[j]);
        __half lo = __float2half(a[j] - __half2float(hi));
        o[2 * j + 0] = hi;
        o[2 * j + 1] = aside ? lo : hi;
    }
    float4* q = (float4*)(out + (size_t)r * K2 + t * 16);
    q[0] = *(const float4*)&o[0];
    q[1] = *(const float4*)&o[8];
}

// ------------------------- mma.sync helpers ----------------------------------
__device__ __forceinline__ uint32_t smem_u32(const void* p) {
    uint32_t a;
    asm("{ .reg .u64 t; cvta.to.shared.u64 t, %1; cvt.u32.u64 %0, t; }" : "=r"(a) : "l"(p));
    return a;
}
__device__ __forceinline__ void cp16(uint32_t dst, const void* src, int nbytes) {
    asm volatile("cp.async.cg.shared.global [%0], [%1], 16, %2;"
                 :: "r"(dst), "l"(src), "r"(nbytes));
}
__device__ __forceinline__ void cp_commit() {
    asm volatile("cp.async.commit_group;" ::: "memory");
}
__device__ __forceinline__ void ldsm_x4(uint32_t* r, uint32_t addr) {
    asm volatile("ldmatrix.sync.aligned.m8n8.x4.shared.b16 {%0,%1,%2,%3}, [%4];"
                 : "=r"(r[0]), "=r"(r[1]), "=r"(r[2]), "=r"(r[3]) : "r"(addr));
}
__device__ __forceinline__ void mma16816(float* c, const uint32_t* a, const uint32_t* b) {
    asm volatile("mma.sync.aligned.m16n8k16.row.col.f32.f16.f16.f32 "
                 "{%0,%1,%2,%3}, {%4,%5,%6,%7}, {%8,%9}, {%0,%1,%2,%3};"
                 : "+f"(c[0]), "+f"(c[1]), "+f"(c[2]), "+f"(c[3])
                 : "r"(a[0]), "r"(a[1]), "r"(a[2]), "r"(a[3]), "r"(b[0]), "r"(b[1]));
}

// --------------------- HMMA GEMM:  C = A2 * B2^T -----------------------------
// A2 [2048,K2] fp16, B2 [N,K2] fp16, C [2048,N] fp32.
// Block 128x128, 8 warps (64x32 warp tile), BK=64 fp16, 3-stage cp.async.
// SMEM: 128B rows with XOR swizzle (16B unit col ^= row&7) -> conflict-free.
// mode: 0 = store, 1 = add (residual), 2 = softplus(acc + bias[col]).
#define BK        64
#define ROWB      128
#define ATILE     (128 * ROWB)              // 16384
#define BUFB      (2 * ATILE)               // 32768 per stage
#define NSTAGE    3
#define GEMM_SMEM (NSTAGE * BUFB)           // 98304

__global__ __launch_bounds__(256, 2)
void gemm_tc(const __half* __restrict__ A2, const __half* __restrict__ B2,
             float* __restrict__ C, int N, int K2, int ldc,
             int mode, const float* __restrict__ bias,
             int split, size_t partStride) {
    extern __shared__ char sm[];
    uint32_t sbase = smem_u32(sm);

    int tid  = threadIdx.x;
    int lane = tid & 31;
    int wid  = tid >> 5;
    int wm   = wid & 1;
    int wn   = wid >> 1;
    int m0   = blockIdx.x * 128;
    int n0   = blockIdx.y * 128;

    int NCtot = K2 / BK;
    int NC    = NCtot / split;
    int c0    = blockIdx.z * NC;
    C += (size_t)blockIdx.z * partStride;

    float acc[4][4][4];
#pragma unroll
    for (int i = 0; i < 4; i++)
#pragma unroll
        for (int j = 0; j < 4; j++)
#pragma unroll
            for (int k = 0; k < 4; k++) acc[i][j][k] = 0.f;

    // swizzled ldmatrix bases: row part only; column (16B unit) applied per-ks
    uint32_t l7x = (uint32_t)(lane & 7) << 4;                 // XOR term (bytes)
    uint32_t a_row = (uint32_t)((wm * 64 + (lane & 15)) * ROWB);
    uint32_t khA   = (uint32_t)(lane >> 4);                   // 0/1 -> k half
    uint32_t b_row = (uint32_t)ATILE +
                     (uint32_t)((wn * 32 + ((lane >> 4) & 1) * 8 + (lane & 7)) * ROWB);
    uint32_t khB   = (uint32_t)((lane >> 3) & 1);

    // cp.async store swizzle: row = u*32 + (tid>>3), q = tid&7
    uint32_t sr7 = (uint32_t)((tid >> 3) & 7);

#define LOAD_CHUNK(c)                                                              \
    {                                                                              \
        int _c = (c);                                                              \
        uint32_t st = sbase + (uint32_t)((_c % NSTAGE) * BUFB);                    \
        const __half* Ag = A2 + (size_t)m0 * K2 + (size_t)(c0 + _c) * BK;          \
        const __half* Bg = B2 + (size_t)(c0 + _c) * BK;                            \
        _Pragma("unroll")                                                          \
        for (int u = 0; u < 4; u++) {                                              \
            int unit = u * 256 + tid;                                              \
            int row = unit >> 3, q = unit & 7;                                     \
            uint32_t dst = st + row * ROWB + (((uint32_t)q ^ sr7) << 4);           \
            cp16(dst, Ag + (size_t)row * K2 + q * 8, 16);                          \
        }                                                                          \
        _Pragma("unroll")                                                          \
        for (int u = 0; u < 4; u++) {                                              \
            int unit = u * 256 + tid;                                              \
            int row = unit >> 3, q = unit & 7;                                     \
            int rb = n0 + row;                                                     \
            int v = (rb < N) ? 16 : 0;                                             \
            int rc = (rb < N) ? rb : 0;                                            \
            uint32_t dst = st + ATILE + row * ROWB + (((uint32_t)q ^ sr7) << 4);   \
            cp16(dst, Bg + (size_t)rc * K2 + q * 8, v);                            \
        }                                                                          \
        cp_commit();                                                               \
    }

    LOAD_CHUNK(0);
    if (NC > 1) LOAD_CHUNK(1);

    for (int c = 0; c < NC; c++) {
        if (c + 1 < NC) asm volatile("cp.async.wait_group 1;" ::: "memory");
        else            asm volatile("cp.async.wait_group 0;" ::: "memory");
        __syncthreads();
        if (c + 2 < NC) LOAD_CHUNK(c + 2);

        uint32_t boff = sbase + (uint32_t)((c % NSTAGE) * BUFB);
#pragma unroll
        for (int ks = 0; ks < 4; ks++) {
            uint32_t ca = ((((uint32_t)ks * 2 + khA) << 4) ^ l7x);
            uint32_t cb = ((((uint32_t)ks * 2 + khB) << 4) ^ l7x);
            uint32_t ka = boff + a_row + ca;
            uint32_t kb = boff + b_row + cb;
            uint32_t af[4][4];
#pragma unroll
            for (int mt = 0; mt < 4; mt++) ldsm_x4(af[mt], ka + mt * 16 * ROWB);
            uint32_t bf[2][4];
#pragma unroll
            for (int p = 0; p < 2; p++) ldsm_x4(bf[p], kb + p * 16 * ROWB);
#pragma unroll
            for (int mt = 0; mt < 4; mt++)
#pragma unroll
                for (int nt = 0; nt < 4; nt++)
                    mma16816(acc[mt][nt], af[mt], &bf[nt >> 1][(nt & 1) * 2]);
        }
    }
#undef LOAD_CHUNK

    int g  = lane >> 2;
    int tg = (lane & 3) * 2;
#pragma unroll
    for (int mt = 0; mt < 4; mt++) {
        int r0 = m0 + wm * 64 + mt * 16 + g;
#pragma unroll
        for (int nt = 0; nt < 4; nt++) {
            int col = n0 + wn * 32 + nt * 8 + tg;
            if (col < N) {
                float* p0 = C + (size_t)r0 * ldc + col;
                float* p1 = p0 + 8 * (size_t)ldc;
                float2 v0 = make_float2(acc[mt][nt][0], acc[mt][nt][1]);
                float2 v1 = make_float2(acc[mt][nt][2], acc[mt][nt][3]);
                if (mode == 1) {
                    float2 o0 = *(float2*)p0, o1 = *(float2*)p1;
                    v0.x += o0.x; v0.y += o0.y; v1.x += o1.x; v1.y += o1.y;
                } else if (mode == 2) {
                    float b0 = bias[col], b1 = bias[col + 1];
                    float t;
                    t = v0.x + b0; v0.x = (t > 20.f) ? t : log1pf(expf(t));
                    t = v0.y + b1; v0.y = (t > 20.f) ? t : log1pf(expf(t));
                    t = v1.x + b0; v1.x = (t > 20.f) ? t : log1pf(expf(t));
                    t = v1.y + b1; v1.y = (t > 20.f) ? t : log1pf(expf(t));
                }
                *(float2*)p0 = v0;
                *(float2*)p1 = v1;
            }
        }
    }
}

// --------------------- split-K partial reduction (x_proj) --------------------
__global__ void reduce_part_kernel() {
    int i = blockIdx.x * 256 + threadIdx.x;
    float s = 0.f;
#pragma unroll
    for (int z = 0; z < 8; z++) s += g_part[z * XP_PART + i];
    g_xdbl[i] = s;
}

// ------------------------------ conv1d(4) + silu -----------------------------
__global__ void conv_kernel(const float* __restrict__ cw, const float* __restrict__ cb) {
    int i = blockIdx.x * 256 + threadIdx.x;
    int l = i / DI, d = i % DI;
    float acc = cb[d];
#pragma unroll
    for (int k = 0; k < 4; k++) {
        int li = l + k - 3;
        if (li >= 0) acc += g_xz[(size_t)li * (2 * DI) + d] * cw[d * 4 + k];
    }
    g_xc[i] = acc / (1.f + expf(-acc));
}

// ------------------------------ selective scan -------------------------------
__global__ __launch_bounds__(256)
void scan_kernel(const float* __restrict__ A_log, float* __restrict__ y) {
    int dloc = threadIdx.x >> 4;
    int n    = threadIdx.x & 15;
    int dbase = blockIdx.x * 16;
    int d = dbase + dloc;
    float a = -__expf(A_log[d * DS + n]);
    float h = 0.f;

    __shared__ float sB[64][16], sC[64][16], sdt[64][16], sxc[64][16];

    for (int l0 = 0; l0 < L_SEQ; l0 += 64) {
        __syncthreads();
        for (int i = threadIdx.x; i < 64 * 16; i += 256) {
            int t = i >> 4, j = i & 15;
            int l = l0 + t;
            sB [t][j] = g_xdbl[(size_t)l * NX + DTR + j];
            sC [t][j] = g_xdbl[(size_t)l * NX + DTR + DS + j];
            sdt[t][j] = g_dt[(size_t)l * DI + dbase + j];
            sxc[t][j] = g_xc[(size_t)l * DI + dbase + j];
        }
        __syncthreads();
#pragma unroll 4
        for (int t = 0; t < 64; t++) {
            float dtv = sdt[t][dloc];
            float xv  = sxc[t][dloc];
            float b   = sB[t][n];
            float c   = sC[t][n];
            h = __expf(dtv * a) * h + dtv * b * xv;
            float p = h * c;
            p += __shfl_xor_sync(0xffffffffu, p, 8, 16);
            p += __shfl_xor_sync(0xffffffffu, p, 4, 16);
            p += __shfl_xor_sync(0xffffffffu, p, 2, 16);
            p += __shfl_xor_sync(0xffffffffu, p, 1, 16);
            if (n == 0) y[(size_t)(l0 + t) * DI + d] = p;
        }
    }
}

// ------------------------------ D-skip + z-gate ------------------------------
__global__ void gate_kernel(const float* __restrict__ dsk) {
    int i = blockIdx.x * 256 + threadIdx.x;
    int l = i / DI, d = i % DI;
    float z  = g_xz[(size_t)l * (2 * DI) + DI + d];
    float sz = z / (1.f + expf(-z));
    g_y[i] = (g_y[i] + dsk[d] * g_xc[i]) * sz;
}

// ============================================================================
static void launch_cvt2(const float* in, __half* out, int R, int K, int ld, int aside) {
    int total = R * (K / 8);
    cvt2_kernel<<<(total + 255) / 256, 256>>>(in, out, K / 8, ld, 2 * K, aside, total);
}

extern "C" void kernel_launch(void* const* d_in, const int* in_sizes, int n_in,
                              void* d_out, int out_size) {
    const int*   ids  = (const int*)  d_in[0];
    const float* emb  = (const float*)d_in[1];
    const float* ln_g = (const float*)d_in[2];
    const float* ln_b = (const float*)d_in[3];
    const float* inw  = (const float*)d_in[4];
    const float* cw   = (const float*)d_in[5];
    const float* cb   = (const float*)d_in[6];
    const float* xpw  = (const float*)d_in[7];
    const float* dtw  = (const float*)d_in[8];
    const float* dtb  = (const float*)d_in[9];
    const float* alog = (const float*)d_in[10];
    const float* dsk  = (const float*)d_in[11];
    const float* outw = (const float*)d_in[12];
    const float* lnfg = (const float*)d_in[13];
    const float* lnfb = (const float*)d_in[14];
    const float* hw   = (const float*)d_in[15];
    float* out = (float*)d_out;

    cudaFuncSetAttribute(gemm_tc, cudaFuncAttributeMaxDynamicSharedMemorySize, GEMM_SMEM);

    float *px, *ph, *pxz, *pxc, *pxdbl, *pdt, *py, *ppart;
    __half *pa2, *pw2, *phead2;
    cudaGetSymbolAddress((void**)&px,    g_x);
    cudaGetSymbolAddress((void**)&ph,    g_h);
    cudaGetSymbolAddress((void**)&pxz,   g_xz);
    cudaGetSymbolAddress((void**)&pxc,   g_xc);
    cudaGetSymbolAddress((void**)&pxdbl, g_xdbl);
    cudaGetSymbolAddress((void**)&pdt,   g_dt);
    cudaGetSymbolAddress((void**)&py,    g_y);
    cudaGetSymbolAddress((void**)&pa2,   g_a2);
    cudaGetSymbolAddress((void**)&pw2,   g_w2);
    cudaGetSymbolAddress((void**)&phead2, g_head2);
    cudaGetSymbolAddress((void**)&ppart, g_part);

    const int EW_BLOCKS = (L_SEQ * DI) / 256;

    embed_kernel<<<L_SEQ, 256>>>(ids, emb);

    for (int l = 0; l < 2; l++) {
        ln_kernel<<<L_SEQ, 256>>>(px, ln_g + l * DM, ln_b + l * DM, ph);

        // in_proj: [2048,1024] x [4096,1024]^T
        launch_cvt2(ph, pa2, L_SEQ, DM, DM, 1);
        launch_cvt2(inw + (size_t)l * 2 * DI * DM, pw2, 2 * DI, DM, DM, 0);
        gemm_tc<<<dim3(16, 32), 256, GEMM_SMEM>>>(
            pa2, pw2, pxz, 2 * DI, 2 * DM, 2 * DI, 0, nullptr, 1, 0);

        conv_kernel<<<EW_BLOCKS, 256>>>(cw + (size_t)l * DI * 4, cb + (size_t)l * DI);

        // x_proj: split-K=8 -> partials -> reduce
        launch_cvt2(pxc, pa2, L_SEQ, DI, DI, 1);
        launch_cvt2(xpw + (size_t)l * NX * DI, pw2, NX, DI, DI, 0);
        gemm_tc<<<dim3(16, 1, 8), 256, GEMM_SMEM>>>(
            pa2, pw2, ppart, NX, 2 * DI, NX, 0, nullptr, 8, XP_PART);
        reduce_part_kernel<<<(L_SEQ * NX) / 256, 256>>>();

        // dt_proj: [2048,64] x [2048,64]^T, fused softplus(acc + dtb)
        launch_cvt2(pxdbl, pa2, L_SEQ, DTR, NX, 1);
        launch_cvt2(dtw + (size_t)l * DI * DTR, pw2, DI, DTR, DTR, 0);
        gemm_tc<<<dim3(16, 16), 256, GEMM_SMEM>>>(
            pa2, pw2, pdt, DI, 2 * DTR, DI, 2, dtb + (size_t)l * DI, 1, 0);

        scan_kernel<<<DI / 16, 256>>>(alog + (size_t)l * DI * DS, py);
        gate_kernel<<<EW_BLOCKS, 256>>>(dsk + (size_t)l * DI);

        // out_proj with residual
        launch_cvt2(py, pa2, L_SEQ, DI, DI, 1);
        launch_cvt2(outw + (size_t)l * DM * DI, pw2, DM, DI, DI, 0);
        gemm_tc<<<dim3(16, 8), 256, GEMM_SMEM>>>(
            pa2, pw2, px, DM, 2 * DI, DM, 1, nullptr, 1, 0);
    }

    // final layernorm + head
    ln_kernel<<<L_SEQ, 256>>>(px, lnfg, lnfb, ph);
    launch_cvt2(ph, pa2, L_SEQ, DM, DM, 1);
    launch_cvt2(hw, phead2, 32000, DM, DM, 0);
    gemm_tc<<<dim3(16, 250), 256, GEMM_SMEM>>>(
        pa2, phead2, out, 32000, 2 * DM, 32000, 0, nullptr, 1, 0);
}